// round 1
// baseline (speedup 1.0000x reference)
#include <cuda_runtime.h>
#include <math.h>
#include <algorithm>

// ---------------- problem constants ----------------
#define BATCH 2
#define LSEQ  196
#define EMBED 768
#define DIMM  3072      // 4*EMBED
#define DINN  6144      // 2*DIMM
#define XRW   12288     // 2*DINN
#define DTR   192
#define DST   16
#define NTOK  392       // BATCH*LSEQ

// ---------------- scratch (device globals; no allocs allowed) ----------------
__device__ float g_patches[NTOK * EMBED];
__device__ float g_xe     [NTOK * EMBED];
__device__ float g_vec    [BATCH * EMBED];
__device__ float g_xm     [NTOK * DIMM];
__device__ float g_xln    [NTOK * DIMM];
__device__ float g_xr     [NTOK * XRW];
__device__ float g_xs     [NTOK * DINN];
__device__ float g_dbl    [NTOK * 224];
__device__ float g_dt     [NTOK * DINN];
__device__ float g_y      [NTOK * DINN];
__device__ float g_pr     [NTOK * EMBED];
__device__ float g_prln   [NTOK * EMBED];
__device__ int   g_sp[LSEQ], g_ra[LSEQ], g_bo[LSEQ];

// ---------------- helpers ----------------
__device__ __forceinline__ float siluf(float v) {
    return v / (1.f + __expf(0.f) * 0.f + expf(-v));  // keep plain expf for accuracy
}

// ---------------- im2col: x (2,3,224,224) -> patches (392, 768) ----------------
__global__ void im2col_kernel(const float* __restrict__ x) {
    int idx = blockIdx.x * blockDim.x + threadIdx.x;
    if (idx >= NTOK * EMBED) return;
    int col = idx % EMBED;          // c*256 + i*16 + j
    int row = idx / EMBED;          // b*196 + l
    int b = row / LSEQ, l = row % LSEQ;
    int ph = l / 14, pw = l % 14;
    int c = col / 256;
    int i = (col % 256) / 16;
    int j = col % 16;
    size_t src = (((size_t)b * 3 + c) * 224 + (ph * 16 + i)) * 224 + (pw * 16 + j);
    g_patches[idx] = x[src];
}

// ---------------- abcde projection: (2,5)@(768,5)^T + b -> g_vec (2,768) ------
__global__ void abcde_kernel(const float* __restrict__ f, const float* __restrict__ w,
                             const float* __restrict__ b) {
    int idx = blockIdx.x * blockDim.x + threadIdx.x;
    if (idx >= BATCH * EMBED) return;
    int bb = idx / EMBED, e = idx % EMBED;
    float s = b[e];
    #pragma unroll
    for (int k = 0; k < 5; k++) s += f[bb * 5 + k] * w[e * 5 + k];
    g_vec[idx] = s;
}

// ---------------- patch epilogue: xe += patch_b + pos + abcde_vec ------------
__global__ void patch_epi_kernel(const float* __restrict__ pb, const float* __restrict__ pos) {
    int idx = blockIdx.x * blockDim.x + threadIdx.x;
    if (idx >= NTOK * EMBED) return;
    int e = idx % EMBED;
    int row = idx / EMBED;
    int b = row / LSEQ, l = row % LSEQ;
    g_xe[idx] += pb[e] + pos[l * EMBED + e] + g_vec[b * EMBED + e];
}

// ---------------- gather: xm[b,l,c*768+e] = xe[b, perm_c(l), e] --------------
__global__ void gather_kernel() {
    int idx = blockIdx.x * blockDim.x + threadIdx.x;
    if (idx >= NTOK * DIMM) return;
    int e = idx % EMBED;
    int c = (idx / EMBED) & 3;
    int l = (idx / DIMM) % LSEQ;
    int b = idx / (DIMM * LSEQ);
    int src_l = (c == 0) ? g_sp[l] : (c == 1) ? g_ra[l] : (c == 2) ? g_bo[l] : l;
    g_xm[idx] = g_xe[((size_t)b * LSEQ + src_l) * EMBED + e];
}

// ---------------- layernorm (generic width), optional input bias ------------
__global__ void ln_kernel(const float* __restrict__ x, const float* __restrict__ inb,
                          const float* __restrict__ w, const float* __restrict__ b,
                          float* __restrict__ out, int D) {
    int row = blockIdx.x;
    const float* xr = x + (size_t)row * D;
    float* orow = out + (size_t)row * D;
    __shared__ float sh[256];
    __shared__ float s_mean, s_inv;
    int tid = threadIdx.x;
    float s = 0.f;
    for (int i = tid; i < D; i += 256) {
        float v = xr[i] + (inb ? inb[i] : 0.f);
        s += v;
    }
    sh[tid] = s; __syncthreads();
    for (int o = 128; o > 0; o >>= 1) { if (tid < o) sh[tid] += sh[tid + o]; __syncthreads(); }
    if (tid == 0) s_mean = sh[0] / (float)D;
    __syncthreads();
    float m = s_mean;
    float v2 = 0.f;
    for (int i = tid; i < D; i += 256) {
        float t = xr[i] + (inb ? inb[i] : 0.f) - m;
        v2 += t * t;
    }
    sh[tid] = v2; __syncthreads();
    for (int o = 128; o > 0; o >>= 1) { if (tid < o) sh[tid] += sh[tid + o]; __syncthreads(); }
    if (tid == 0) s_inv = 1.f / sqrtf(sh[0] / (float)D + 1e-5f);
    __syncthreads();
    float inv = s_inv;
    for (int i = tid; i < D; i += 256) {
        float t = (xr[i] + (inb ? inb[i] : 0.f) - m) * inv;
        orow[i] = t * w[i] + b[i];
    }
}

// ---------------- GEMM: C[M,N] = A[M,K] * W[N,K]^T (NT), split-K, modes -----
// mode 0: store, 1: store + bias[n], 2: atomicAdd, 3: softplus(acc+bias[n])
__global__ __launch_bounds__(256)
void gemm_nt(const float* __restrict__ A, const float* __restrict__ W,
             float* __restrict__ C, const float* __restrict__ bias,
             int M, int N, int K, int lda, int mode) {
    __shared__ float As[2][8][128];
    __shared__ float Ws[2][8][128];
    const int tid = threadIdx.x;
    const int m0 = blockIdx.y * 128;
    const int n0 = blockIdx.x * 128;
    const int kchunk = K / gridDim.z;
    const int kbeg = blockIdx.z * kchunk;

    const int lrow = tid >> 1;
    const int lcol = (tid & 1) << 2;

    const float* Ap = A + (size_t)(m0 + lrow) * lda + kbeg + lcol;
    const float* Wp = W + (size_t)(n0 + lrow) * K + kbeg + lcol;
    const bool av = (m0 + lrow) < M;
    const bool wv = (n0 + lrow) < N;

    const int tx = tid & 15;
    const int ty = tid >> 4;

    float acc[8][8];
    #pragma unroll
    for (int i = 0; i < 8; i++)
        #pragma unroll
        for (int j = 0; j < 8; j++) acc[i][j] = 0.f;

    const int nk = kchunk >> 3;
    float4 zero4 = make_float4(0.f, 0.f, 0.f, 0.f);
    float4 a_ld = av ? *(const float4*)Ap : zero4;
    float4 w_ld = wv ? *(const float4*)Wp : zero4;
    As[0][lcol + 0][lrow] = a_ld.x; As[0][lcol + 1][lrow] = a_ld.y;
    As[0][lcol + 2][lrow] = a_ld.z; As[0][lcol + 3][lrow] = a_ld.w;
    Ws[0][lcol + 0][lrow] = w_ld.x; Ws[0][lcol + 1][lrow] = w_ld.y;
    Ws[0][lcol + 2][lrow] = w_ld.z; Ws[0][lcol + 3][lrow] = w_ld.w;
    __syncthreads();

    int buf = 0;
    for (int kt = 0; kt < nk; kt++) {
        if (kt + 1 < nk) {
            a_ld = av ? *(const float4*)(Ap + (kt + 1) * 8) : zero4;
            w_ld = wv ? *(const float4*)(Wp + (kt + 1) * 8) : zero4;
        }
        #pragma unroll
        for (int kk = 0; kk < 8; kk++) {
            float4 a0 = *(const float4*)&As[buf][kk][ty * 4];
            float4 a1 = *(const float4*)&As[buf][kk][64 + ty * 4];
            float4 b0 = *(const float4*)&Ws[buf][kk][tx * 4];
            float4 b1 = *(const float4*)&Ws[buf][kk][64 + tx * 4];
            float am[8] = {a0.x, a0.y, a0.z, a0.w, a1.x, a1.y, a1.z, a1.w};
            float bn[8] = {b0.x, b0.y, b0.z, b0.w, b1.x, b1.y, b1.z, b1.w};
            #pragma unroll
            for (int i = 0; i < 8; i++)
                #pragma unroll
                for (int j = 0; j < 8; j++)
                    acc[i][j] = fmaf(am[i], bn[j], acc[i][j]);
        }
        if (kt + 1 < nk) {
            buf ^= 1;
            As[buf][lcol + 0][lrow] = a_ld.x; As[buf][lcol + 1][lrow] = a_ld.y;
            As[buf][lcol + 2][lrow] = a_ld.z; As[buf][lcol + 3][lrow] = a_ld.w;
            Ws[buf][lcol + 0][lrow] = w_ld.x; Ws[buf][lcol + 1][lrow] = w_ld.y;
            Ws[buf][lcol + 2][lrow] = w_ld.z; Ws[buf][lcol + 3][lrow] = w_ld.w;
            __syncthreads();
        }
    }

    #pragma unroll
    for (int i = 0; i < 8; i++) {
        int row = m0 + ((i < 4) ? (ty * 4 + i) : (64 + ty * 4 + i - 4));
        if (row >= M) continue;
        #pragma unroll
        for (int j = 0; j < 8; j++) {
            int col = n0 + ((j < 4) ? (tx * 4 + j) : (64 + tx * 4 + j - 4));
            if (col >= N) continue;
            float v = acc[i][j];
            size_t o = (size_t)row * N + col;
            if (mode == 0) C[o] = v;
            else if (mode == 1) C[o] = v + bias[col];
            else if (mode == 2) atomicAdd(&C[o], v);
            else {
                float t = v + bias[col];
                C[o] = (t > 20.f) ? t : log1pf(expf(t));
            }
        }
    }
}

// ---------------- causal depthwise conv (k=4) + bias + SiLU -----------------
__global__ void conv_silu_kernel(const float* __restrict__ w, const float* __restrict__ bias) {
    int idx = blockIdx.x * blockDim.x + threadIdx.x;
    if (idx >= NTOK * DINN) return;
    int d = idx % DINN;
    int t = (idx / DINN) % LSEQ;
    int b = idx / (DINN * LSEQ);
    const float* wd = w + (size_t)d * 4;
    float acc = bias[d];
    size_t rb = ((size_t)b * LSEQ) * XRW + d;
    #pragma unroll
    for (int k = 0; k < 4; k++) {
        int tt = t - 3 + k;
        if (tt >= 0) acc = fmaf(wd[k], g_xr[rb + (size_t)tt * XRW], acc);
    }
    g_xs[idx] = acc / (1.f + expf(-acc));
}

// ---------------- selective scan ----------------
// block = 256 threads = 16 channels x 16 states; 768 blocks (2 batches x 384)
__global__ void scan_kernel(const float* __restrict__ alog, const float* __restrict__ Dp) {
    int tid = threadIdx.x;
    int n  = tid & 15;
    int ci = tid >> 4;
    int blk = blockIdx.x;
    int b = blk / 384;
    int d = (blk % 384) * 16 + ci;

    float Ac = -expf(alog[(size_t)d * DST + n]);
    float Dv = Dp[d];
    float st = 0.f;
    size_t base = (size_t)b * LSEQ;
    for (int t = 0; t < LSEQ; t++) {
        size_t row = base + t;
        float dtv = g_dt[row * DINN + d];
        float xv  = g_xs[row * DINN + d];
        float Bv  = g_dbl[row * 224 + 192 + n];
        float Cv  = g_dbl[row * 224 + 208 + n];
        st = fmaf(st, expf(dtv * Ac), dtv * Bv * xv);
        float yp = st * Cv;
        yp += __shfl_down_sync(0xffffffffu, yp, 8, 16);
        yp += __shfl_down_sync(0xffffffffu, yp, 4, 16);
        yp += __shfl_down_sync(0xffffffffu, yp, 2, 16);
        yp += __shfl_down_sync(0xffffffffu, yp, 1, 16);
        if (n == 0) {
            float r = g_xr[row * XRW + DINN + d];   // res half of in_proj output
            float yf = fmaf(xv, Dv, yp);
            yf = yf * (r / (1.f + expf(-r)));       // * silu(res)
            g_y[row * DINN + d] = yf;
        }
    }
}

// ---------------- final mean over tokens ----------------
__global__ void mean_kernel(float* __restrict__ out) {
    int idx = blockIdx.x * blockDim.x + threadIdx.x;
    if (idx >= BATCH * EMBED) return;
    int b = idx / EMBED, e = idx % EMBED;
    float s = 0.f;
    for (int t = 0; t < LSEQ; t++)
        s += g_prln[((size_t)b * LSEQ + t) * EMBED + e];
    out[idx] = s / (float)LSEQ;
}

// ---------------- host: permutation index construction (mirrors numpy) ------
static void build_spiral(int* sp) {
    bool seen[LSEQ] = {false};
    int cnt = 0;
    for (int r = 0; r < 14; r++) {
        int n = (2 * r > 8) ? 2 * r : 8;
        double step = (2.0 * M_PI) / (double)n;
        for (int k = 0; k < n; k++) {
            double ang = (double)k * step;
            int h = (int)(7.0 + (double)r * cos(ang));
            int w = (int)(7.0 + (double)r * sin(ang));
            if (h >= 0 && h < 14 && w >= 0 && w < 14) {
                int i = h * 14 + w;
                if (!seen[i]) { seen[i] = true; sp[cnt++] = i; }
            }
        }
    }
    for (int i = 0; i < LSEQ; i++) if (!seen[i]) sp[cnt++] = i;
}

struct RItem { double d, a; int i; };

static void build_radial(int* ra) {
    RItem items[LSEQ];
    for (int h = 0; h < 14; h++)
        for (int w = 0; w < 14; w++) {
            int i = h * 14 + w;
            double dy = (double)(h - 7), dx = (double)(w - 7);
            items[i].d = sqrt(dy * dy + dx * dx);
            items[i].a = atan2(dy, dx);
            items[i].i = i;
        }
    std::stable_sort(items, items + LSEQ, [](const RItem& x, const RItem& y) {
        if (x.d != y.d) return x.d > y.d;
        return x.a < y.a;
    });
    for (int i = 0; i < LSEQ; i++) ra[i] = items[i].i;
}

static void build_boundary(int* bo) {
    int cnt = 0;
    for (int h = 0; h < 14; h++)
        for (int w = 0; w < 14; w++)
            if (h == 0 || h == 13 || w == 0 || w == 13) bo[cnt++] = h * 14 + w;
    for (int h = 0; h < 14; h++)
        for (int w = 0; w < 14; w++)
            if (!(h == 0 || h == 13 || w == 0 || w == 13)) bo[cnt++] = h * 14 + w;
}

// ---------------- launcher ----------------
extern "C" void kernel_launch(void* const* d_in, const int* in_sizes, int n_in,
                              void* d_out, int out_size) {
    // setup_inputs() dict insertion order; dt_proj_b appended last.
    const float* x       = (const float*)d_in[0];
    const float* abf     = (const float*)d_in[1];
    const float* patch_w = (const float*)d_in[2];
    const float* patch_b = (const float*)d_in[3];
    const float* pos     = (const float*)d_in[4];
    const float* aw      = (const float*)d_in[5];
    const float* ab      = (const float*)d_in[6];
    const float* ln_w    = (const float*)d_in[7];
    const float* ln_b    = (const float*)d_in[8];
    const float* inw     = (const float*)d_in[9];
    const float* convw   = (const float*)d_in[10];
    const float* convb   = (const float*)d_in[11];
    const float* xpw     = (const float*)d_in[12];
    const float* dtw     = (const float*)d_in[13];
    const float* alog    = (const float*)d_in[14];
    const float* dpar    = (const float*)d_in[15];
    const float* outw    = (const float*)d_in[16];
    const float* projw   = (const float*)d_in[17];
    const float* projb   = (const float*)d_in[18];
    const float* normw   = (const float*)d_in[19];
    const float* normb   = (const float*)d_in[20];
    const float* dtb     = (const float*)d_in[21];

    // permutation tables (host compute, capturable H2D copy; static storage
    // persists for graph replays)
    static int hsp[LSEQ], hra[LSEQ], hbo[LSEQ];
    build_spiral(hsp);
    build_radial(hra);
    build_boundary(hbo);
    cudaMemcpyToSymbolAsync(g_sp, hsp, sizeof(hsp), 0, cudaMemcpyHostToDevice, 0);
    cudaMemcpyToSymbolAsync(g_ra, hra, sizeof(hra), 0, cudaMemcpyHostToDevice, 0);
    cudaMemcpyToSymbolAsync(g_bo, hbo, sizeof(hbo), 0, cudaMemcpyHostToDevice, 0);

    // scratch pointers for GEMM/memset
    void *p_patches, *p_xe, *p_xm, *p_xln, *p_xr, *p_xs, *p_dbl, *p_dt, *p_y, *p_pr, *p_prln;
    cudaGetSymbolAddress(&p_patches, g_patches);
    cudaGetSymbolAddress(&p_xe, g_xe);
    cudaGetSymbolAddress(&p_xm, g_xm);
    cudaGetSymbolAddress(&p_xln, g_xln);
    cudaGetSymbolAddress(&p_xr, g_xr);
    cudaGetSymbolAddress(&p_xs, g_xs);
    cudaGetSymbolAddress(&p_dbl, g_dbl);
    cudaGetSymbolAddress(&p_dt, g_dt);
    cudaGetSymbolAddress(&p_y, g_y);
    cudaGetSymbolAddress(&p_pr, g_pr);
    cudaGetSymbolAddress(&p_prln, g_prln);

    const int T256 = 256;

    // patch embedding as GEMM (im2col) + epilogue
    im2col_kernel<<<(NTOK * EMBED + T256 - 1) / T256, T256>>>(x);
    abcde_kernel<<<(BATCH * EMBED + T256 - 1) / T256, T256>>>(abf, aw, ab);
    cudaMemsetAsync(p_xe, 0, (size_t)NTOK * EMBED * sizeof(float), 0);
    gemm_nt<<<dim3(6, 4, 4), T256>>>((const float*)p_patches, patch_w, (float*)p_xe,
                                     nullptr, NTOK, EMBED, EMBED, EMBED, 2);
    patch_epi_kernel<<<(NTOK * EMBED + T256 - 1) / T256, T256>>>(patch_b, pos);
    gather_kernel<<<(NTOK * DIMM + T256 - 1) / T256, T256>>>();

    for (int l = 0; l < 2; l++) {
        ln_kernel<<<NTOK, T256>>>((const float*)p_xm, nullptr,
                                  ln_w + (size_t)l * DIMM, ln_b + (size_t)l * DIMM,
                                  (float*)p_xln, DIMM);
        // in_proj: (392,3072) x (12288,3072)^T
        gemm_nt<<<dim3(96, 4, 1), T256>>>((const float*)p_xln,
                                          inw + (size_t)l * XRW * DIMM,
                                          (float*)p_xr, nullptr,
                                          NTOK, XRW, DIMM, DIMM, 0);
        conv_silu_kernel<<<(NTOK * DINN + T256 - 1) / T256, T256>>>(
            convw + (size_t)l * DINN * 4, convb + (size_t)l * DINN);
        // x_proj: (392,6144) x (224,6144)^T, split-K 16
        cudaMemsetAsync(p_dbl, 0, (size_t)NTOK * 224 * sizeof(float), 0);
        gemm_nt<<<dim3(2, 4, 16), T256>>>((const float*)p_xs,
                                          xpw + (size_t)l * 224 * DINN,
                                          (float*)p_dbl, nullptr,
                                          NTOK, 224, DINN, DINN, 2);
        // dt_proj + softplus bias: A = dbl[:, :192] (lda=224)
        gemm_nt<<<dim3(48, 4, 1), T256>>>((const float*)p_dbl,
                                          dtw + (size_t)l * DINN * DTR,
                                          (float*)p_dt, dtb + (size_t)l * DINN,
                                          NTOK, DINN, DTR, 224, 3);
        scan_kernel<<<768, T256>>>(alog + (size_t)l * DINN * DST,
                                   dpar + (size_t)l * DINN);
        // out_proj residual accumulate into xm, split-K 4
        gemm_nt<<<dim3(24, 4, 4), T256>>>((const float*)p_y,
                                          outw + (size_t)l * DIMM * DINN,
                                          (float*)p_xm, nullptr,
                                          NTOK, DIMM, DINN, DINN, 2);
    }

    // final projection, split-K 8
    cudaMemsetAsync(p_pr, 0, (size_t)NTOK * EMBED * sizeof(float), 0);
    gemm_nt<<<dim3(6, 4, 8), T256>>>((const float*)p_xm, projw, (float*)p_pr,
                                     nullptr, NTOK, EMBED, DIMM, DIMM, 2);
    ln_kernel<<<NTOK, T256>>>((const float*)p_pr, projb, normw, normb,
                              (float*)p_prln, EMBED);
    mean_kernel<<<(BATCH * EMBED + T256 - 1) / T256, T256>>>((float*)d_out);
}

// round 3
// speedup vs baseline: 1.8235x; 1.8235x over previous
#include <cuda_runtime.h>
#include <cuda_bf16.h>
#include <math.h>
#include <algorithm>
#include <cstdint>

// ---------------- problem constants ----------------
#define BATCH 2
#define LSEQ  196
#define EMBED 768
#define DIMM  3072      // 4*EMBED
#define DINN  6144      // 2*DIMM
#define XRW   12288     // 2*DINN
#define DTR   192
#define DST   16
#define NTOK  392       // BATCH*LSEQ
#define PADM  512       // padded row count for 128-row M tiles

// ---------------- scratch (device globals; no allocs allowed) ----------------
__device__ float g_patches[PADM * EMBED];
__device__ float g_xe     [PADM * EMBED];
__device__ float g_vec    [BATCH * EMBED];
__device__ float g_xm     [PADM * DIMM];
__device__ float g_xln    [PADM * DIMM];
__device__ float g_xr     [PADM * XRW];
__device__ float g_xs     [PADM * DINN];
__device__ float g_dbl    [PADM * 224];
__device__ float g_dt     [PADM * DINN];
__device__ float g_y      [PADM * DINN];
__device__ float g_pr     [PADM * EMBED];
__device__ float g_prln   [NTOK * EMBED];
__device__ int   g_sp[LSEQ], g_ra[LSEQ], g_bo[LSEQ];

// ---------------- weight hi/lo bf16 planes (precomputed per call) ------------
#define SZ_INW  (2 * XRW * DIMM)       // 75,497,472
#define SZ_OUTW (2 * DIMM * DINN)      // 37,748,736
#define SZ_XPW  (2 * 224 * DINN)       // 2,752,512
#define SZ_DTW  (2 * DINN * DTR)       // 2,359,296
#define SZ_PRW  (EMBED * DIMM)         // 2,359,296
#define SZ_PAW  (EMBED * EMBED)        // 589,824
__device__ __nv_bfloat16 g_wih[SZ_INW],  g_wil[SZ_INW];
__device__ __nv_bfloat16 g_woh[SZ_OUTW], g_wol[SZ_OUTW];
__device__ __nv_bfloat16 g_wxh[SZ_XPW],  g_wxl[SZ_XPW];
__device__ __nv_bfloat16 g_wdh[SZ_DTW],  g_wdl[SZ_DTW];
__device__ __nv_bfloat16 g_wph[SZ_PRW],  g_wpl[SZ_PRW];
__device__ __nv_bfloat16 g_wch[SZ_PAW],  g_wcl[SZ_PAW];

// ---------------- hi/lo split convert (vectorized) ----------------
__global__ void cvt_kernel(const float* __restrict__ src,
                           __nv_bfloat16* __restrict__ hi,
                           __nv_bfloat16* __restrict__ lo, int n4) {
    int i = blockIdx.x * blockDim.x + threadIdx.x;
    int stride = gridDim.x * blockDim.x;
    for (; i < n4; i += stride) {
        float4 v = ((const float4*)src)[i];
        __nv_bfloat16 h0 = __float2bfloat16(v.x);
        __nv_bfloat16 h1 = __float2bfloat16(v.y);
        __nv_bfloat16 h2 = __float2bfloat16(v.z);
        __nv_bfloat16 h3 = __float2bfloat16(v.w);
        __nv_bfloat162* H = (__nv_bfloat162*)hi;
        __nv_bfloat162* L = (__nv_bfloat162*)lo;
        H[2 * i]     = __nv_bfloat162(h0, h1);
        H[2 * i + 1] = __nv_bfloat162(h2, h3);
        L[2 * i]     = __nv_bfloat162(__float2bfloat16(v.x - __bfloat162float(h0)),
                                      __float2bfloat16(v.y - __bfloat162float(h1)));
        L[2 * i + 1] = __nv_bfloat162(__float2bfloat16(v.z - __bfloat162float(h2)),
                                      __float2bfloat16(v.w - __bfloat162float(h3)));
    }
}

// ================= bf16 mma.sync GEMM =================
// C[M,N] = A[Mpad,K](fp32) * W[N,K]^T with 3-term hi/lo split.
// Block tile 128x128, BK=32 fp32. 8 warps, each 64x32 (m16n8k16 fragments).
// grid = (Ntiles, 4, zsplit). modes: 0 store, 1 +bias, 2 atomicAdd, 3 softplus(+bias).
#define PLA 10240            // plane stride: 128 rows * 80B
#define ROWB 80              // smem row stride (5x16B -> conflict-free ldmatrix)

__device__ __forceinline__ uint32_t smem_u32(const void* p) {
    uint32_t a;
    asm("{ .reg .u64 t; cvta.to.shared.u64 t, %1; cvt.u32.u64 %0, t; }" : "=r"(a) : "l"(p));
    return a;
}
__device__ __forceinline__ uint32_t pack_bf(__nv_bfloat16 a, __nv_bfloat16 b) {
    return (uint32_t)__bfloat16_as_ushort(a) | ((uint32_t)__bfloat16_as_ushort(b) << 16);
}
#define LDSM_X4(r, addr) \
    asm volatile("ldmatrix.sync.aligned.m8n8.x4.shared.b16 {%0,%1,%2,%3}, [%4];" \
        : "=r"((r)[0]), "=r"((r)[1]), "=r"((r)[2]), "=r"((r)[3]) : "r"(addr))
#define MMA16816(d, a, b) \
    asm volatile("mma.sync.aligned.m16n8k16.row.col.f32.bf16.bf16.f32 " \
        "{%0,%1,%2,%3}, {%4,%5,%6,%7}, {%8,%9}, {%0,%1,%2,%3};" \
        : "+f"((d)[0]), "+f"((d)[1]), "+f"((d)[2]), "+f"((d)[3]) \
        : "r"((a)[0]), "r"((a)[1]), "r"((a)[2]), "r"((a)[3]), "r"((b)[0]), "r"((b)[1]))

__global__ __launch_bounds__(256, 1)
void gemm_mma(const float* __restrict__ A, int lda,
              const __nv_bfloat16* __restrict__ Bh,
              const __nv_bfloat16* __restrict__ Bl,
              float* __restrict__ C, int ldc,
              const float* __restrict__ bias,
              int Nvalid, int Ktot, int mode)
{
    __shared__ __align__(16) char smem[4 * PLA];   // Ah, Al, Bh, Bl planes
    const int tid  = threadIdx.x;
    const int wid  = tid >> 5;
    const int lane = tid & 31;
    const int wm = wid & 1;        // 2 warp rows of 64
    const int wn = wid >> 1;       // 4 warp cols of 32
    const int m0 = blockIdx.y * 128;
    const int n0 = blockIdx.x * 128;
    const int nk = Ktot / (32 * (int)gridDim.z);
    const int kbeg = blockIdx.z * nk * 32;

    const uint32_t sb = smem_u32(smem);
    const uint32_t sAh = sb, sAl = sb + PLA, sBh = sb + 2 * PLA, sBl = sb + 3 * PLA;

    // ---- staging roles: each thread owns one row, half the k-chunk ----
    const int lrow = tid >> 1;
    const int half = tid & 1;
    const float* Ap = A + (size_t)(m0 + lrow) * lda + kbeg + half * 16;
    const bool bvalid = (n0 + lrow) < Nvalid;
    const __nv_bfloat16* Bhp = Bh + (size_t)(n0 + lrow) * Ktot + kbeg + half * 16;
    const __nv_bfloat16* Blp = Bl + (size_t)(n0 + lrow) * Ktot + kbeg + half * 16;

    float4 a_st[4];
    uint4  bh_st[2], bl_st[2];
    const uint4 z4 = make_uint4(0, 0, 0, 0);

    auto load_stage = [&](int c) {
        const float* ap = Ap + c * 32;
        a_st[0] = *(const float4*)(ap + 0);
        a_st[1] = *(const float4*)(ap + 4);
        a_st[2] = *(const float4*)(ap + 8);
        a_st[3] = *(const float4*)(ap + 12);
        if (bvalid) {
            bh_st[0] = *(const uint4*)(Bhp + c * 32);
            bh_st[1] = *(const uint4*)(Bhp + c * 32 + 8);
            bl_st[0] = *(const uint4*)(Blp + c * 32);
            bl_st[1] = *(const uint4*)(Blp + c * 32 + 8);
        } else { bh_st[0] = bh_st[1] = bl_st[0] = bl_st[1] = z4; }
    };
    auto store_stage = [&]() {
        float f[16];
        *(float4*)(f + 0)  = a_st[0]; *(float4*)(f + 4)  = a_st[1];
        *(float4*)(f + 8)  = a_st[2]; *(float4*)(f + 12) = a_st[3];
        #pragma unroll
        for (int cc = 0; cc < 2; cc++) {
            uint32_t hw[4], lw[4];
            #pragma unroll
            for (int j = 0; j < 4; j++) {
                float v0 = f[cc * 8 + 2 * j], v1 = f[cc * 8 + 2 * j + 1];
                __nv_bfloat16 h0 = __float2bfloat16(v0), h1 = __float2bfloat16(v1);
                hw[j] = pack_bf(h0, h1);
                lw[j] = pack_bf(__float2bfloat16(v0 - __bfloat162float(h0)),
                                __float2bfloat16(v1 - __bfloat162float(h1)));
            }
            uint32_t off = lrow * ROWB + (half * 2 + cc) * 16;
            asm volatile("st.shared.v4.b32 [%0], {%1,%2,%3,%4};" ::
                "r"(sAh + off), "r"(hw[0]), "r"(hw[1]), "r"(hw[2]), "r"(hw[3]));
            asm volatile("st.shared.v4.b32 [%0], {%1,%2,%3,%4};" ::
                "r"(sAl + off), "r"(lw[0]), "r"(lw[1]), "r"(lw[2]), "r"(lw[3]));
        }
        #pragma unroll
        for (int cc = 0; cc < 2; cc++) {
            uint32_t off = lrow * ROWB + (half * 2 + cc) * 16;
            uint4 h = bh_st[cc], l = bl_st[cc];
            asm volatile("st.shared.v4.b32 [%0], {%1,%2,%3,%4};" ::
                "r"(sBh + off), "r"(h.x), "r"(h.y), "r"(h.z), "r"(h.w));
            asm volatile("st.shared.v4.b32 [%0], {%1,%2,%3,%4};" ::
                "r"(sBl + off), "r"(l.x), "r"(l.y), "r"(l.z), "r"(l.w));
        }
    };

    float d[4][4][4];
    #pragma unroll
    for (int i = 0; i < 4; i++)
        #pragma unroll
        for (int j = 0; j < 4; j++)
            #pragma unroll
            for (int q = 0; q < 4; q++) d[i][j][q] = 0.f;

    // ldmatrix base addresses (per thread)
    const int arow = wm * 64 + (lane & 15);
    const int asel = lane >> 4;                 // k-chunk select
    const int brow = wn * 32 + (lane >> 4) * 8 + (lane & 7);
    const int bsel = (lane >> 3) & 1;

    load_stage(0);
    for (int c = 0; c < nk; c++) {
        store_stage();
        __syncthreads();
        if (c + 1 < nk) load_stage(c + 1);

        #pragma unroll
        for (int ks = 0; ks < 2; ks++) {
            uint32_t ah[4][4], al[4][4], bh[4][2], bl[4][2];
            #pragma unroll
            for (int mt = 0; mt < 4; mt++) {
                uint32_t off = (arow + mt * 16) * ROWB + (ks * 2 + asel) * 16;
                LDSM_X4(ah[mt], sAh + off);
                LDSM_X4(al[mt], sAl + off);
            }
            #pragma unroll
            for (int np = 0; np < 2; np++) {
                uint32_t off = (brow + np * 16) * ROWB + (ks * 2 + bsel) * 16;
                uint32_t th[4], tl[4];
                LDSM_X4(th, sBh + off);
                LDSM_X4(tl, sBl + off);
                bh[2 * np][0] = th[0]; bh[2 * np][1] = th[1];
                bh[2 * np + 1][0] = th[2]; bh[2 * np + 1][1] = th[3];
                bl[2 * np][0] = tl[0]; bl[2 * np][1] = tl[1];
                bl[2 * np + 1][0] = tl[2]; bl[2 * np + 1][1] = tl[3];
            }
            #pragma unroll
            for (int mt = 0; mt < 4; mt++)
                #pragma unroll
                for (int nt = 0; nt < 4; nt++) {
                    MMA16816(d[mt][nt], ah[mt], bh[nt]);
                    MMA16816(d[mt][nt], ah[mt], bl[nt]);
                    MMA16816(d[mt][nt], al[mt], bh[nt]);
                }
        }
        __syncthreads();
    }

    // ---- epilogue ----
    const int g = lane >> 2, q = lane & 3;
    #pragma unroll
    for (int mt = 0; mt < 4; mt++) {
        int r0 = m0 + wm * 64 + mt * 16 + g;
        #pragma unroll
        for (int nt = 0; nt < 4; nt++) {
            int c0 = n0 + wn * 32 + nt * 8 + q * 2;
            if (c0 >= Nvalid) continue;
            bool c1v = (c0 + 1) < Nvalid;
            float v00 = d[mt][nt][0], v01 = d[mt][nt][1];
            float v10 = d[mt][nt][2], v11 = d[mt][nt][3];
            float* p0 = C + (size_t)r0 * ldc + c0;
            float* p1 = C + (size_t)(r0 + 8) * ldc + c0;
            if (mode == 2) {
                atomicAdd(p0, v00); if (c1v) atomicAdd(p0 + 1, v01);
                atomicAdd(p1, v10); if (c1v) atomicAdd(p1 + 1, v11);
            } else {
                if (mode == 1) {
                    v00 += bias[c0]; v10 += bias[c0];
                    if (c1v) { v01 += bias[c0 + 1]; v11 += bias[c0 + 1]; }
                } else if (mode == 3) {
                    float b0 = bias[c0], b1 = c1v ? bias[c0 + 1] : 0.f;
                    float t;
                    t = v00 + b0; v00 = (t > 20.f) ? t : log1pf(expf(t));
                    t = v10 + b0; v10 = (t > 20.f) ? t : log1pf(expf(t));
                    t = v01 + b1; v01 = (t > 20.f) ? t : log1pf(expf(t));
                    t = v11 + b1; v11 = (t > 20.f) ? t : log1pf(expf(t));
                }
                if (c1v) {
                    *(float2*)p0 = make_float2(v00, v01);
                    *(float2*)p1 = make_float2(v10, v11);
                } else { *p0 = v00; *p1 = v10; }
            }
        }
    }
}

// ================= elementwise / misc kernels =================
__global__ void im2col_kernel(const float* __restrict__ x) {
    int idx = blockIdx.x * blockDim.x + threadIdx.x;
    if (idx >= NTOK * EMBED) return;
    int col = idx % EMBED;
    int row = idx / EMBED;
    int b = row / LSEQ, l = row % LSEQ;
    int ph = l / 14, pw = l % 14;
    int c = col / 256;
    int i = (col % 256) / 16;
    int j = col % 16;
    size_t src = (((size_t)b * 3 + c) * 224 + (ph * 16 + i)) * 224 + (pw * 16 + j);
    g_patches[row * EMBED + col] = x[src];
}

__global__ void abcde_kernel(const float* __restrict__ f, const float* __restrict__ w,
                             const float* __restrict__ b) {
    int idx = blockIdx.x * blockDim.x + threadIdx.x;
    if (idx >= BATCH * EMBED) return;
    int bb = idx / EMBED, e = idx % EMBED;
    float s = b[e];
    #pragma unroll
    for (int k = 0; k < 5; k++) s += f[bb * 5 + k] * w[e * 5 + k];
    g_vec[idx] = s;
}

__global__ void patch_epi_kernel(const float* __restrict__ pb, const float* __restrict__ pos) {
    int idx = blockIdx.x * blockDim.x + threadIdx.x;
    if (idx >= NTOK * EMBED) return;
    int e = idx % EMBED;
    int row = idx / EMBED;
    int b = row / LSEQ, l = row % LSEQ;
    g_xe[idx] += pb[e] + pos[l * EMBED + e] + g_vec[b * EMBED + e];
}

__global__ void gather_kernel() {
    int idx = blockIdx.x * blockDim.x + threadIdx.x;
    if (idx >= NTOK * DIMM) return;
    int e = idx % EMBED;
    int c = (idx / EMBED) & 3;
    int l = (idx / DIMM) % LSEQ;
    int b = idx / (DIMM * LSEQ);
    int src_l = (c == 0) ? g_sp[l] : (c == 1) ? g_ra[l] : (c == 2) ? g_bo[l] : l;
    g_xm[idx] = g_xe[((size_t)b * LSEQ + src_l) * EMBED + e];
}

__global__ void ln_kernel(const float* __restrict__ x, const float* __restrict__ inb,
                          const float* __restrict__ w, const float* __restrict__ b,
                          float* __restrict__ out, int D) {
    int row = blockIdx.x;
    const float* xr = x + (size_t)row * D;
    float* orow = out + (size_t)row * D;
    __shared__ float sh[256];
    __shared__ float s_mean, s_inv;
    int tid = threadIdx.x;
    float s = 0.f;
    for (int i = tid; i < D; i += 256) s += xr[i] + (inb ? inb[i] : 0.f);
    sh[tid] = s; __syncthreads();
    for (int o = 128; o > 0; o >>= 1) { if (tid < o) sh[tid] += sh[tid + o]; __syncthreads(); }
    if (tid == 0) s_mean = sh[0] / (float)D;
    __syncthreads();
    float m = s_mean;
    float v2 = 0.f;
    for (int i = tid; i < D; i += 256) {
        float t = xr[i] + (inb ? inb[i] : 0.f) - m;
        v2 += t * t;
    }
    sh[tid] = v2; __syncthreads();
    for (int o = 128; o > 0; o >>= 1) { if (tid < o) sh[tid] += sh[tid + o]; __syncthreads(); }
    if (tid == 0) s_inv = 1.f / sqrtf(sh[0] / (float)D + 1e-5f);
    __syncthreads();
    float inv = s_inv;
    for (int i = tid; i < D; i += 256) {
        float t = (xr[i] + (inb ? inb[i] : 0.f) - m) * inv;
        orow[i] = t * w[i] + b[i];
    }
}

__global__ void conv_silu_kernel(const float* __restrict__ w, const float* __restrict__ bias) {
    int idx = blockIdx.x * blockDim.x + threadIdx.x;
    if (idx >= NTOK * DINN) return;
    int d = idx % DINN;
    int t = (idx / DINN) % LSEQ;
    int b = idx / (DINN * LSEQ);
    const float* wd = w + (size_t)d * 4;
    float acc = bias[d];
    size_t rb = ((size_t)b * LSEQ) * XRW + d;
    #pragma unroll
    for (int k = 0; k < 4; k++) {
        int tt = t - 3 + k;
        if (tt >= 0) acc = fmaf(wd[k], g_xr[rb + (size_t)tt * XRW], acc);
    }
    g_xs[idx] = acc / (1.f + expf(-acc));
}

__global__ void scan_kernel(const float* __restrict__ alog, const float* __restrict__ Dp) {
    int tid = threadIdx.x;
    int n  = tid & 15;
    int ci = tid >> 4;
    int blk = blockIdx.x;
    int b = blk / 384;
    int d = (blk % 384) * 16 + ci;

    float Ac = -expf(alog[(size_t)d * DST + n]);
    float Dv = Dp[d];
    float st = 0.f;
    size_t base = (size_t)b * LSEQ;
    for (int t = 0; t < LSEQ; t++) {
        size_t row = base + t;
        float dtv = g_dt[row * DINN + d];
        float xv  = g_xs[row * DINN + d];
        float Bv  = g_dbl[row * 224 + 192 + n];
        float Cv  = g_dbl[row * 224 + 208 + n];
        st = fmaf(st, expf(dtv * Ac), dtv * Bv * xv);
        float yp = st * Cv;
        yp += __shfl_down_sync(0xffffffffu, yp, 8, 16);
        yp += __shfl_down_sync(0xffffffffu, yp, 4, 16);
        yp += __shfl_down_sync(0xffffffffu, yp, 2, 16);
        yp += __shfl_down_sync(0xffffffffu, yp, 1, 16);
        if (n == 0) {
            float r = g_xr[row * XRW + DINN + d];
            float yf = fmaf(xv, Dv, yp);
            yf = yf * (r / (1.f + expf(-r)));
            g_y[row * DINN + d] = yf;
        }
    }
}

__global__ void mean_kernel(float* __restrict__ out) {
    int idx = blockIdx.x * blockDim.x + threadIdx.x;
    if (idx >= BATCH * EMBED) return;
    int b = idx / EMBED, e = idx % EMBED;
    float s = 0.f;
    for (int t = 0; t < LSEQ; t++)
        s += g_prln[((size_t)b * LSEQ + t) * EMBED + e];
    out[idx] = s / (float)LSEQ;
}

// ---------------- host: permutation index construction (mirrors numpy) ------
static void build_spiral(int* sp) {
    bool seen[LSEQ] = {false};
    int cnt = 0;
    for (int r = 0; r < 14; r++) {
        int n = (2 * r > 8) ? 2 * r : 8;
        double step = (2.0 * M_PI) / (double)n;
        for (int k = 0; k < n; k++) {
            double ang = (double)k * step;
            int h = (int)(7.0 + (double)r * cos(ang));
            int w = (int)(7.0 + (double)r * sin(ang));
            if (h >= 0 && h < 14 && w >= 0 && w < 14) {
                int i = h * 14 + w;
                if (!seen[i]) { seen[i] = true; sp[cnt++] = i; }
            }
        }
    }
    for (int i = 0; i < LSEQ; i++) if (!seen[i]) sp[cnt++] = i;
}
struct RItem { double d, a; int i; };
static void build_radial(int* ra) {
    RItem items[LSEQ];
    for (int h = 0; h < 14; h++)
        for (int w = 0; w < 14; w++) {
            int i = h * 14 + w;
            double dy = (double)(h - 7), dx = (double)(w - 7);
            items[i].d = sqrt(dy * dy + dx * dx);
            items[i].a = atan2(dy, dx);
            items[i].i = i;
        }
    std::stable_sort(items, items + LSEQ, [](const RItem& x, const RItem& y) {
        if (x.d != y.d) return x.d > y.d;
        return x.a < y.a;
    });
    for (int i = 0; i < LSEQ; i++) ra[i] = items[i].i;
}
static void build_boundary(int* bo) {
    int cnt = 0;
    for (int h = 0; h < 14; h++)
        for (int w = 0; w < 14; w++)
            if (h == 0 || h == 13 || w == 0 || w == 13) bo[cnt++] = h * 14 + w;
    for (int h = 0; h < 14; h++)
        for (int w = 0; w < 14; w++)
            if (!(h == 0 || h == 13 || w == 0 || w == 13)) bo[cnt++] = h * 14 + w;
}

// ---------------- launcher ----------------
extern "C" void kernel_launch(void* const* d_in, const int* in_sizes, int n_in,
                              void* d_out, int out_size) {
    const float* x       = (const float*)d_in[0];
    const float* abf     = (const float*)d_in[1];
    const float* patch_w = (const float*)d_in[2];
    const float* patch_b = (const float*)d_in[3];
    const float* pos     = (const float*)d_in[4];
    const float* aw      = (const float*)d_in[5];
    const float* ab      = (const float*)d_in[6];
    const float* ln_w    = (const float*)d_in[7];
    const float* ln_b    = (const float*)d_in[8];
    const float* inw     = (const float*)d_in[9];
    const float* convw   = (const float*)d_in[10];
    const float* convb   = (const float*)d_in[11];
    const float* xpw     = (const float*)d_in[12];
    const float* dtw     = (const float*)d_in[13];
    const float* alog    = (const float*)d_in[14];
    const float* dpar    = (const float*)d_in[15];
    const float* outw    = (const float*)d_in[16];
    const float* projw   = (const float*)d_in[17];
    const float* projb   = (const float*)d_in[18];
    const float* normw   = (const float*)d_in[19];
    const float* normb   = (const float*)d_in[20];
    const float* dtb     = (const float*)d_in[21];

    static int hsp[LSEQ], hra[LSEQ], hbo[LSEQ];
    build_spiral(hsp);
    build_radial(hra);
    build_boundary(hbo);
    cudaMemcpyToSymbolAsync(g_sp, hsp, sizeof(hsp), 0, cudaMemcpyHostToDevice, 0);
    cudaMemcpyToSymbolAsync(g_ra, hra, sizeof(hra), 0, cudaMemcpyHostToDevice, 0);
    cudaMemcpyToSymbolAsync(g_bo, hbo, sizeof(hbo), 0, cudaMemcpyHostToDevice, 0);

    void *p_patches, *p_xe, *p_xm, *p_xln, *p_xr, *p_xs, *p_dbl, *p_dt, *p_y, *p_pr, *p_prln;
    cudaGetSymbolAddress(&p_patches, g_patches);
    cudaGetSymbolAddress(&p_xe, g_xe);
    cudaGetSymbolAddress(&p_xm, g_xm);
    cudaGetSymbolAddress(&p_xln, g_xln);
    cudaGetSymbolAddress(&p_xr, g_xr);
    cudaGetSymbolAddress(&p_xs, g_xs);
    cudaGetSymbolAddress(&p_dbl, g_dbl);
    cudaGetSymbolAddress(&p_dt, g_dt);
    cudaGetSymbolAddress(&p_y, g_y);
    cudaGetSymbolAddress(&p_pr, g_pr);
    cudaGetSymbolAddress(&p_prln, g_prln);

    // weight plane pointers
    void *w_ih, *w_il, *w_oh, *w_ol, *w_xh, *w_xl, *w_dh, *w_dl, *w_ph, *w_pl, *w_ch, *w_cl;
    cudaGetSymbolAddress(&w_ih, g_wih); cudaGetSymbolAddress(&w_il, g_wil);
    cudaGetSymbolAddress(&w_oh, g_woh); cudaGetSymbolAddress(&w_ol, g_wol);
    cudaGetSymbolAddress(&w_xh, g_wxh); cudaGetSymbolAddress(&w_xl, g_wxl);
    cudaGetSymbolAddress(&w_dh, g_wdh); cudaGetSymbolAddress(&w_dl, g_wdl);
    cudaGetSymbolAddress(&w_ph, g_wph); cudaGetSymbolAddress(&w_pl, g_wpl);
    cudaGetSymbolAddress(&w_ch, g_wch); cudaGetSymbolAddress(&w_cl, g_wcl);

    const int T256 = 256;
    const int PAD = PADM - NTOK;

    // weight hi/lo splits (recomputed deterministically every call)
    cvt_kernel<<<2048, 256>>>(inw,     (__nv_bfloat16*)w_ih, (__nv_bfloat16*)w_il, SZ_INW / 4);
    cvt_kernel<<<2048, 256>>>(outw,    (__nv_bfloat16*)w_oh, (__nv_bfloat16*)w_ol, SZ_OUTW / 4);
    cvt_kernel<<<512,  256>>>(xpw,     (__nv_bfloat16*)w_xh, (__nv_bfloat16*)w_xl, SZ_XPW / 4);
    cvt_kernel<<<512,  256>>>(dtw,     (__nv_bfloat16*)w_dh, (__nv_bfloat16*)w_dl, SZ_DTW / 4);
    cvt_kernel<<<512,  256>>>(projw,   (__nv_bfloat16*)w_ph, (__nv_bfloat16*)w_pl, SZ_PRW / 4);
    cvt_kernel<<<256,  256>>>(patch_w, (__nv_bfloat16*)w_ch, (__nv_bfloat16*)w_cl, SZ_PAW / 4);

    // zero pad rows of every GEMM A-operand buffer
    cudaMemsetAsync((float*)p_patches + (size_t)NTOK * EMBED, 0, (size_t)PAD * EMBED * 4, 0);
    cudaMemsetAsync((float*)p_xln     + (size_t)NTOK * DIMM,  0, (size_t)PAD * DIMM  * 4, 0);
    cudaMemsetAsync((float*)p_xs      + (size_t)NTOK * DINN,  0, (size_t)PAD * DINN  * 4, 0);
    cudaMemsetAsync((float*)p_y       + (size_t)NTOK * DINN,  0, (size_t)PAD * DINN  * 4, 0);
    cudaMemsetAsync((float*)p_xm      + (size_t)NTOK * DIMM,  0, (size_t)PAD * DIMM  * 4, 0);

    // patch embedding + epilogue
    im2col_kernel<<<(NTOK * EMBED + T256 - 1) / T256, T256>>>(x);
    abcde_kernel<<<(BATCH * EMBED + T256 - 1) / T256, T256>>>(abf, aw, ab);
    cudaMemsetAsync(p_xe, 0, (size_t)PADM * EMBED * 4, 0);
    gemm_mma<<<dim3(6, 4, 3), T256>>>((const float*)p_patches, EMBED,
                                      (const __nv_bfloat16*)w_ch, (const __nv_bfloat16*)w_cl,
                                      (float*)p_xe, EMBED, nullptr, EMBED, EMBED, 2);
    patch_epi_kernel<<<(NTOK * EMBED + T256 - 1) / T256, T256>>>(patch_b, pos);
    gather_kernel<<<(NTOK * DIMM + T256 - 1) / T256, T256>>>();

    for (int l = 0; l < 2; l++) {
        ln_kernel<<<NTOK, T256>>>((const float*)p_xm, nullptr,
                                  ln_w + (size_t)l * DIMM, ln_b + (size_t)l * DIMM,
                                  (float*)p_xln, DIMM);
        // in_proj: (512,3072) x (12288,3072)^T -> xr (store)
        gemm_mma<<<dim3(96, 4, 1), T256>>>((const float*)p_xln, DIMM,
                                           (const __nv_bfloat16*)w_ih + (size_t)l * XRW * DIMM,
                                           (const __nv_bfloat16*)w_il + (size_t)l * XRW * DIMM,
                                           (float*)p_xr, XRW, nullptr, XRW, DIMM, 0);
        conv_silu_kernel<<<(NTOK * DINN + T256 - 1) / T256, T256>>>(
            convw + (size_t)l * DINN * 4, convb + (size_t)l * DINN);
        // x_proj: split-K 12, atomic
        cudaMemsetAsync(p_dbl, 0, (size_t)PADM * 224 * 4, 0);
        gemm_mma<<<dim3(2, 4, 12), T256>>>((const float*)p_xs, DINN,
                                           (const __nv_bfloat16*)w_xh + (size_t)l * 224 * DINN,
                                           (const __nv_bfloat16*)w_xl + (size_t)l * 224 * DINN,
                                           (float*)p_dbl, 224, nullptr, 224, DINN, 2);
        // dt_proj + softplus(+bias): A = dbl[:, :192] (lda=224)
        gemm_mma<<<dim3(48, 4, 1), T256>>>((const float*)p_dbl, 224,
                                           (const __nv_bfloat16*)w_dh + (size_t)l * DINN * DTR,
                                           (const __nv_bfloat16*)w_dl + (size_t)l * DINN * DTR,
                                           (float*)p_dt, DINN,
                                           dtb + (size_t)l * DINN, DINN, DTR, 3);
        scan_kernel<<<768, T256>>>(alog + (size_t)l * DINN * DST,
                                   dpar + (size_t)l * DINN);
        // out_proj residual accumulate into xm, split-K 2, atomic
        gemm_mma<<<dim3(24, 4, 2), T256>>>((const float*)p_y, DINN,
                                           (const __nv_bfloat16*)w_oh + (size_t)l * DIMM * DINN,
                                           (const __nv_bfloat16*)w_ol + (size_t)l * DIMM * DINN,
                                           (float*)p_xm, DIMM, nullptr, DIMM, DINN, 2);
    }

    // final projection, split-K 6, atomic
    cudaMemsetAsync(p_pr, 0, (size_t)PADM * EMBED * 4, 0);
    gemm_mma<<<dim3(6, 4, 6), T256>>>((const float*)p_xm, DIMM,
                                      (const __nv_bfloat16*)w_ph, (const __nv_bfloat16*)w_pl,
                                      (float*)p_pr, EMBED, nullptr, EMBED, DIMM, 2);
    ln_kernel<<<NTOK, T256>>>((const float*)p_pr, projb, normw, normb,
                              (float*)p_prln, EMBED);
    mean_kernel<<<(BATCH * EMBED + T256 - 1) / T256, T256>>>((float*)d_out);
}